// round 5
// baseline (speedup 1.0000x reference)
#include <cuda_runtime.h>
#include <cuda_bf16.h>
#include <cstdint>

// out[t,h] = sum_{g<2} sum_{k<2} buf[g, idx[t,k], h]
// buf: (2, 16384, 4096) fp32 ; idx: (8192, 2) int32 ; out: (8192, 4096) fp32
//
// HBM-bound gather+sum. ~452 MB compulsory DRAM traffic (dup rows hit L2).
// This version: 8 independent float4 loads per thread (MLP=8) and streaming
// stores (__stcs) so write-once output doesn't evict gather rows from L2.

static constexpr int NTOKENS = 8192;
static constexpr int HIDDEN  = 4096;
static constexpr int M_FULL  = 16384;
static constexpr int H4      = HIDDEN / 4;          // 1024 float4 per row
static constexpr long long GSTRIDE4 = (long long)M_FULL * H4;  // float4 stride between groups

__global__ __launch_bounds__(256) void gather_sum_kernel(
    const float4* __restrict__ buf,
    const int* __restrict__ idx,
    float4* __restrict__ out)
{
    const int t  = blockIdx.x;
    const int h4 = blockIdx.y * 512 + threadIdx.x;   // first of two positions

    // Broadcast index loads (same address across block)
    const int i0 = __ldg(&idx[t * 2 + 0]);
    const int i1 = __ldg(&idx[t * 2 + 1]);

    const long long r0 = (long long)i0 * H4 + h4;
    const long long r1 = (long long)i1 * H4 + h4;

    // 8 independent loads -> MLP=8, deep L1tex queue, hides DRAM latency
    float4 a0 = __ldg(&buf[r0]);
    float4 b0 = __ldg(&buf[r1]);
    float4 c0 = __ldg(&buf[GSTRIDE4 + r0]);
    float4 d0 = __ldg(&buf[GSTRIDE4 + r1]);
    float4 a1 = __ldg(&buf[r0 + 256]);
    float4 b1 = __ldg(&buf[r1 + 256]);
    float4 c1 = __ldg(&buf[GSTRIDE4 + r0 + 256]);
    float4 d1 = __ldg(&buf[GSTRIDE4 + r1 + 256]);

    float4 s0, s1;
    s0.x = (a0.x + b0.x) + (c0.x + d0.x);
    s0.y = (a0.y + b0.y) + (c0.y + d0.y);
    s0.z = (a0.z + b0.z) + (c0.z + d0.z);
    s0.w = (a0.w + b0.w) + (c0.w + d0.w);
    s1.x = (a1.x + b1.x) + (c1.x + d1.x);
    s1.y = (a1.y + b1.y) + (c1.y + d1.y);
    s1.z = (a1.z + b1.z) + (c1.z + d1.z);
    s1.w = (a1.w + b1.w) + (c1.w + d1.w);

    const long long o = (long long)t * H4 + h4;
    // Streaming stores: evict-first, keep L2 capacity for gather-row reuse
    __stcs(&out[o], s0);
    __stcs(&out[o + 256], s1);
}

extern "C" void kernel_launch(void* const* d_in, const int* in_sizes, int n_in,
                              void* d_out, int out_size)
{
    const float4* buf = (const float4*)d_in[0];
    const int*    idx = (const int*)d_in[1];
    float4*       out = (float4*)d_out;

    dim3 grid(NTOKENS, H4 / 512);   // 8192 x 2 blocks, 256 thr, 2 float4 each
    gather_sum_kernel<<<grid, 256>>>(buf, idx, out);
}

// round 6
// speedup vs baseline: 1.0713x; 1.0713x over previous
#include <cuda_runtime.h>
#include <cuda_bf16.h>
#include <cstdint>

// out[t,h] = sum_{g<2} sum_{k<2} buf[g, idx[t,k], h]
// buf: (2, 16384, 4096) fp32 ; idx: (8192, 2) int32 ; out: (8192, 4096) fp32
//
// HBM-bound gather+sum, compulsory DRAM traffic ~452 MB (dup rows hit L2).
// Geometry: grid=(8192 tokens, 4 h-segments), 256 thr, 1 float4/thread.
// CTAs schedule x-fastest -> execution sweeps h-segments in phases; per-phase
// gather footprint = ~20.7K unique rows x 4KB = 83 MB < 126 MB L2, so
// duplicate-row reuse is captured in L2. Output uses streaming stores so the
// write-once data doesn't evict gather rows.

static constexpr int NTOKENS = 8192;
static constexpr int HIDDEN  = 4096;
static constexpr int M_FULL  = 16384;
static constexpr int H4      = HIDDEN / 4;          // 1024 float4 per row
static constexpr long long GSTRIDE4 = (long long)M_FULL * H4;  // float4 stride between groups

__global__ __launch_bounds__(256) void gather_sum_kernel(
    const float4* __restrict__ buf,
    const int* __restrict__ idx,
    float4* __restrict__ out)
{
    const int t  = blockIdx.x;
    const int h4 = blockIdx.y * 256 + threadIdx.x;   // 0..1023

    // Broadcast index loads (same address across block)
    const int i0 = __ldg(&idx[t * 2 + 0]);
    const int i1 = __ldg(&idx[t * 2 + 1]);

    const long long r0 = (long long)i0 * H4 + h4;
    const long long r1 = (long long)i1 * H4 + h4;

    // 4 independent loads -> MLP=4, hides DRAM latency
    float4 a = __ldg(&buf[r0]);
    float4 b = __ldg(&buf[r1]);
    float4 c = __ldg(&buf[GSTRIDE4 + r0]);
    float4 d = __ldg(&buf[GSTRIDE4 + r1]);

    float4 r;
    r.x = (a.x + b.x) + (c.x + d.x);
    r.y = (a.y + b.y) + (c.y + d.y);
    r.z = (a.z + b.z) + (c.z + d.z);
    r.w = (a.w + b.w) + (c.w + d.w);

    // Streaming store: evict-first, keep L2 capacity for gather-row reuse
    __stcs(&out[(long long)t * H4 + h4], r);
}

extern "C" void kernel_launch(void* const* d_in, const int* in_sizes, int n_in,
                              void* d_out, int out_size)
{
    const float4* buf = (const float4*)d_in[0];
    const int*    idx = (const int*)d_in[1];
    float4*       out = (float4*)d_out;

    dim3 grid(NTOKENS, H4 / 256);   // 8192 x 4 blocks
    gather_sum_kernel<<<grid, 256>>>(buf, idx, out);
}

// round 7
// speedup vs baseline: 1.1055x; 1.0319x over previous
#include <cuda_runtime.h>
#include <cuda_bf16.h>
#include <cstdint>

// out[t,h] = sum_{g<2} sum_{k<2} buf[g, idx[t,k], h]
// buf: (2, 16384, 4096) fp32 ; idx: (8192, 2) int32 ; out: (8192, 4096) fp32
//
// HBM-bound gather+sum at the compulsory-traffic floor (~460 MB DRAM).
// Geometry: grid=(8192 tokens, 4 h-segments of 4KB), block=128, each thread
// handles TWO float4 positions inside the same 4KB segment -> MLP=8 per
// thread without growing the per-phase L2 gather footprint (83 MB < 126 MB).
// Streaming stores keep write-once output from evicting gather rows.

static constexpr int NTOKENS = 8192;
static constexpr int HIDDEN  = 4096;
static constexpr int M_FULL  = 16384;
static constexpr int H4      = HIDDEN / 4;          // 1024 float4 per row
static constexpr long long GSTRIDE4 = (long long)M_FULL * H4;  // float4 stride between groups

__global__ __launch_bounds__(128) void gather_sum_kernel(
    const float4* __restrict__ buf,
    const int* __restrict__ idx,
    float4* __restrict__ out)
{
    const int t  = blockIdx.x;
    const int h4 = blockIdx.y * 256 + threadIdx.x;   // first of two positions in this 4KB segment

    // Broadcast index loads (same address across block)
    const int i0 = __ldg(&idx[t * 2 + 0]);
    const int i1 = __ldg(&idx[t * 2 + 1]);

    const long long r0 = (long long)i0 * H4 + h4;
    const long long r1 = (long long)i1 * H4 + h4;

    // 8 independent loads -> deep L1tex queue, hides DRAM latency
    float4 a0 = __ldg(&buf[r0]);
    float4 b0 = __ldg(&buf[r1]);
    float4 c0 = __ldg(&buf[GSTRIDE4 + r0]);
    float4 d0 = __ldg(&buf[GSTRIDE4 + r1]);
    float4 a1 = __ldg(&buf[r0 + 128]);
    float4 b1 = __ldg(&buf[r1 + 128]);
    float4 c1 = __ldg(&buf[GSTRIDE4 + r0 + 128]);
    float4 d1 = __ldg(&buf[GSTRIDE4 + r1 + 128]);

    float4 s0, s1;
    s0.x = (a0.x + b0.x) + (c0.x + d0.x);
    s0.y = (a0.y + b0.y) + (c0.y + d0.y);
    s0.z = (a0.z + b0.z) + (c0.z + d0.z);
    s0.w = (a0.w + b0.w) + (c0.w + d0.w);
    s1.x = (a1.x + b1.x) + (c1.x + d1.x);
    s1.y = (a1.y + b1.y) + (c1.y + d1.y);
    s1.z = (a1.z + b1.z) + (c1.z + d1.z);
    s1.w = (a1.w + b1.w) + (c1.w + d1.w);

    const long long o = (long long)t * H4 + h4;
    // Streaming stores: evict-first, keep L2 capacity for gather-row reuse
    __stcs(&out[o], s0);
    __stcs(&out[o + 128], s1);
}

extern "C" void kernel_launch(void* const* d_in, const int* in_sizes, int n_in,
                              void* d_out, int out_size)
{
    const float4* buf = (const float4*)d_in[0];
    const int*    idx = (const int*)d_in[1];
    float4*       out = (float4*)d_out;

    dim3 grid(NTOKENS, H4 / 256);   // 8192 x 4 blocks, 128 thr, 2 float4 each
    gather_sum_kernel<<<grid, 128>>>(buf, idx, out);
}